// round 1
// baseline (speedup 1.0000x reference)
#include <cuda_runtime.h>
#include <math_constants.h>
#include <cstdint>

// Problem constants
constexpr int B_ = 4;
constexpr int T_ = 2048;
constexpr int E_ = 1024;
constexpr int H_ = 16;
constexpr int S_ = 64;

// Scratch (static device globals: allowed; no runtime allocation)
__device__ float g_Q[(size_t)B_ * H_ * T_ * S_];   // 32 MB, (b,h,t,s), pre-scaled
__device__ float g_K[(size_t)B_ * H_ * T_ * S_];   // 32 MB, (b,h,t,s), pre-scaled
__device__ float g_V[(size_t)B_ * H_ * T_ * S_];   // 32 MB, (b,h,t,s)
__device__ float g_C[(size_t)B_ * T_ * E_];        // 32 MB, attention context (b,t,e)

// ---------------------------------------------------------------------------
// Kernel 1: QKV projection.
//   q[b,h,t,o] = (1/E^0.25) * sum_i x[b,t,h*S+i] * Wq[o,i]   (same for k; v unscaled)
// Grid: (T/64, H, B), 256 threads. Dynamic smem: (3*64 + 64) * 65 floats.
// ---------------------------------------------------------------------------
__global__ __launch_bounds__(256) void qkv_kernel(const float* __restrict__ x,
                                                  const float* __restrict__ Wq,
                                                  const float* __restrict__ Wk,
                                                  const float* __restrict__ Wv) {
    extern __shared__ float sm[];
    float(*sW)[65] = (float(*)[65])sm;               // rows 0..63 Wq, 64..127 Wk, 128..191 Wv
    float(*sX)[65] = (float(*)[65])(sm + 192 * 65);  // 64 x-rows

    const int t0 = blockIdx.x * 64;
    const int h = blockIdx.y, b = blockIdx.z;
    const int tid = threadIdx.x;

    for (int i = tid; i < S_ * S_; i += 256) {
        int r = i >> 6, c = i & 63;
        sW[r][c] = Wq[i];
        sW[64 + r][c] = Wk[i];
        sW[128 + r][c] = Wv[i];
    }
    const float* xp = x + ((size_t)b * T_ + t0) * E_ + h * S_;
    for (int i = tid; i < 64 * S_; i += 256) {
        int r = i >> 6, c = i & 63;
        sX[r][c] = xp[(size_t)r * E_ + c];
    }
    __syncthreads();

    const int tx = tid & 15, ty = tid >> 4;  // thread tile: 4 rows x 4 cols
    float aq[4][4] = {}, ak[4][4] = {}, av[4][4] = {};

#pragma unroll 8
    for (int i = 0; i < S_; ++i) {
        float xv[4], wq[4], wk[4], wv[4];
#pragma unroll
        for (int ii = 0; ii < 4; ++ii) xv[ii] = sX[ty * 4 + ii][i];
#pragma unroll
        for (int jj = 0; jj < 4; ++jj) {
            wq[jj] = sW[tx * 4 + jj][i];
            wk[jj] = sW[64 + tx * 4 + jj][i];
            wv[jj] = sW[128 + tx * 4 + jj][i];
        }
#pragma unroll
        for (int ii = 0; ii < 4; ++ii)
#pragma unroll
            for (int jj = 0; jj < 4; ++jj) {
                aq[ii][jj] += xv[ii] * wq[jj];
                ak[ii][jj] += xv[ii] * wk[jj];
                av[ii][jj] += xv[ii] * wv[jj];
            }
    }

    const float inv_scale = 0.17677669529663688f;  // 1 / 1024^0.25
    const size_t ob = ((size_t)(b * H_ + h) * T_ + t0) * S_;
#pragma unroll
    for (int ii = 0; ii < 4; ++ii)
#pragma unroll
        for (int jj = 0; jj < 4; ++jj) {
            size_t idx = ob + (size_t)(ty * 4 + ii) * S_ + tx * 4 + jj;
            g_Q[idx] = aq[ii][jj] * inv_scale;
            g_K[idx] = ak[ii][jj] * inv_scale;
            g_V[idx] = av[ii][jj];
        }
}

// ---------------------------------------------------------------------------
// Kernel 2: Flash attention (full/non-causal), one (b,h) per block.y/z,
// Q tile = 128 rows, K/V tile = 64 rows. 256 threads, 8x4 register tiles.
// Grid: (T/128, H, B). Dynamic smem: (128 + 128 + 64 + 64) * 65 floats = 99840 B.
// ---------------------------------------------------------------------------
__global__ __launch_bounds__(256, 2) void attn_kernel() {
    extern __shared__ float sm[];
    float(*sQ)[65] = (float(*)[65])sm;                // 128 rows
    float(*sP)[65] = (float(*)[65])(sm + 128 * 65);   // 128 rows
    float(*sK)[65] = (float(*)[65])(sm + 256 * 65);   // 64 rows
    float(*sV)[65] = (float(*)[65])(sm + 320 * 65);   // 64 rows

    const int q0 = blockIdx.x * 128;
    const int h = blockIdx.y, b = blockIdx.z;
    const size_t base = (size_t)(b * H_ + h) * T_ * S_;
    const int tid = threadIdx.x;
    const int tx = tid & 15, ty = tid >> 4;  // rows ty*8..+7, cols tx*4..+3

    for (int i = tid; i < 128 * S_; i += 256) {
        int r = i >> 6, c = i & 63;
        sQ[r][c] = g_Q[base + (size_t)(q0 + r) * S_ + c];
    }

    float m_i[8], l_i[8], oacc[8][4];
#pragma unroll
    for (int ii = 0; ii < 8; ++ii) {
        m_i[ii] = -CUDART_INF_F;
        l_i[ii] = 0.f;
#pragma unroll
        for (int jj = 0; jj < 4; ++jj) oacc[ii][jj] = 0.f;
    }
    __syncthreads();

    for (int kt = 0; kt < T_; kt += 64) {
        // load K/V tile
        for (int i = tid; i < 64 * S_; i += 256) {
            int r = i >> 6, c = i & 63;
            size_t g = base + (size_t)(kt + r) * S_ + c;
            sK[r][c] = g_K[g];
            sV[r][c] = g_V[g];
        }
        __syncthreads();

        // scores: S = Q K^T  (128 x 64)
        float sacc[8][4] = {};
#pragma unroll 8
        for (int i = 0; i < S_; ++i) {
            float qv[8], kv[4];
#pragma unroll
            for (int ii = 0; ii < 8; ++ii) qv[ii] = sQ[ty * 8 + ii][i];
#pragma unroll
            for (int jj = 0; jj < 4; ++jj) kv[jj] = sK[tx * 4 + jj][i];
#pragma unroll
            for (int ii = 0; ii < 8; ++ii)
#pragma unroll
                for (int jj = 0; jj < 4; ++jj) sacc[ii][jj] += qv[ii] * kv[jj];
        }

        // online softmax update per row
#pragma unroll
        for (int ii = 0; ii < 8; ++ii) {
            float rm = fmaxf(fmaxf(sacc[ii][0], sacc[ii][1]),
                             fmaxf(sacc[ii][2], sacc[ii][3]));
            rm = fmaxf(rm, __shfl_xor_sync(0xffffffffu, rm, 8));
            rm = fmaxf(rm, __shfl_xor_sync(0xffffffffu, rm, 4));
            rm = fmaxf(rm, __shfl_xor_sync(0xffffffffu, rm, 2));
            rm = fmaxf(rm, __shfl_xor_sync(0xffffffffu, rm, 1));
            float mnew = fmaxf(m_i[ii], rm);
            float corr = __expf(m_i[ii] - mnew);  // exp(-inf)=0 on first tile
            m_i[ii] = mnew;

            float rs = 0.f;
#pragma unroll
            for (int jj = 0; jj < 4; ++jj) {
                float p = __expf(sacc[ii][jj] - mnew);
                sP[ty * 8 + ii][tx * 4 + jj] = p;
                rs += p;
            }
            rs += __shfl_xor_sync(0xffffffffu, rs, 8);
            rs += __shfl_xor_sync(0xffffffffu, rs, 4);
            rs += __shfl_xor_sync(0xffffffffu, rs, 2);
            rs += __shfl_xor_sync(0xffffffffu, rs, 1);
            l_i[ii] = l_i[ii] * corr + rs;
#pragma unroll
            for (int jj = 0; jj < 4; ++jj) oacc[ii][jj] *= corr;
        }
        __syncthreads();  // sP visible to all

        // O += P @ V  (128 x 64)
#pragma unroll 8
        for (int k = 0; k < 64; ++k) {
            float pv[8], vv[4];
#pragma unroll
            for (int ii = 0; ii < 8; ++ii) pv[ii] = sP[ty * 8 + ii][k];
#pragma unroll
            for (int jj = 0; jj < 4; ++jj) vv[jj] = sV[k][tx * 4 + jj];
#pragma unroll
            for (int ii = 0; ii < 8; ++ii)
#pragma unroll
                for (int jj = 0; jj < 4; ++jj) oacc[ii][jj] += pv[ii] * vv[jj];
        }
        __syncthreads();  // done with sK/sV/sP before next tile
    }

    // epilogue: normalize and write context in (b,t,e) layout
#pragma unroll
    for (int ii = 0; ii < 8; ++ii) {
        float inv = 1.0f / l_i[ii];
        int q = q0 + ty * 8 + ii;
        size_t ob = ((size_t)b * T_ + q) * E_ + h * S_ + tx * 4;
#pragma unroll
        for (int jj = 0; jj < 4; ++jj) g_C[ob + jj] = oacc[ii][jj] * inv;
    }
}

// ---------------------------------------------------------------------------
// Kernel 3: output projection  Y[m, o] = sum_e C[m, e] * Wp[o, e] + bp[o]
// M = B*T = 8192, N = K = 1024. Tile: 128(M) x 64(N), k-chunks of 64.
// Grid: (M/128, N/64), 256 threads. Dynamic smem: (128 + 64) * 65 floats.
// ---------------------------------------------------------------------------
__global__ __launch_bounds__(256, 2) void proj_kernel(const float* __restrict__ Wp,
                                                      const float* __restrict__ bp,
                                                      float* __restrict__ out) {
    extern __shared__ float sm[];
    float(*sA)[65] = (float(*)[65])sm;               // 128 rows of C
    float(*sB)[65] = (float(*)[65])(sm + 128 * 65);  // 64 rows of Wp

    const int m0 = blockIdx.x * 128;
    const int n0 = blockIdx.y * 64;
    const int tid = threadIdx.x;
    const int tx = tid & 15, ty = tid >> 4;

    float acc[8][4] = {};

    for (int kc = 0; kc < E_; kc += 64) {
        for (int i = tid; i < 128 * 64; i += 256) {
            int r = i >> 6, c = i & 63;
            sA[r][c] = g_C[(size_t)(m0 + r) * E_ + kc + c];
        }
        for (int i = tid; i < 64 * 64; i += 256) {
            int r = i >> 6, c = i & 63;
            sB[r][c] = Wp[(size_t)(n0 + r) * E_ + kc + c];
        }
        __syncthreads();

#pragma unroll 8
        for (int i = 0; i < 64; ++i) {
            float av[8], bv[4];
#pragma unroll
            for (int ii = 0; ii < 8; ++ii) av[ii] = sA[ty * 8 + ii][i];
#pragma unroll
            for (int jj = 0; jj < 4; ++jj) bv[jj] = sB[tx * 4 + jj][i];
#pragma unroll
            for (int ii = 0; ii < 8; ++ii)
#pragma unroll
                for (int jj = 0; jj < 4; ++jj) acc[ii][jj] += av[ii] * bv[jj];
        }
        __syncthreads();
    }

    float bias[4];
#pragma unroll
    for (int jj = 0; jj < 4; ++jj) bias[jj] = bp[n0 + tx * 4 + jj];
#pragma unroll
    for (int ii = 0; ii < 8; ++ii) {
        size_t ob = (size_t)(m0 + ty * 8 + ii) * E_ + n0 + tx * 4;
#pragma unroll
        for (int jj = 0; jj < 4; ++jj) out[ob + jj] = acc[ii][jj] + bias[jj];
    }
}

// ---------------------------------------------------------------------------
// kernel_launch: inputs in metadata order x, Wk, Wq, Wv, Wp, bp
// ---------------------------------------------------------------------------
extern "C" void kernel_launch(void* const* d_in, const int* in_sizes, int n_in,
                              void* d_out, int out_size) {
    (void)in_sizes; (void)n_in; (void)out_size;
    const float* x  = (const float*)d_in[0];
    const float* Wk = (const float*)d_in[1];
    const float* Wq = (const float*)d_in[2];
    const float* Wv = (const float*)d_in[3];
    const float* Wp = (const float*)d_in[4];
    const float* bp = (const float*)d_in[5];
    float* out = (float*)d_out;

    constexpr int SMEM_QKV  = 256 * 65 * 4;  // 66560 B
    constexpr int SMEM_ATTN = 384 * 65 * 4;  // 99840 B
    constexpr int SMEM_PROJ = 192 * 65 * 4;  // 49920 B

    // Host-side attribute sets (idempotent, not stream ops; safe under capture)
    cudaFuncSetAttribute(qkv_kernel, cudaFuncAttributeMaxDynamicSharedMemorySize, SMEM_QKV);
    cudaFuncSetAttribute(attn_kernel, cudaFuncAttributeMaxDynamicSharedMemorySize, SMEM_ATTN);
    cudaFuncSetAttribute(proj_kernel, cudaFuncAttributeMaxDynamicSharedMemorySize, SMEM_PROJ);

    qkv_kernel<<<dim3(T_ / 64, H_, B_), 256, SMEM_QKV>>>(x, Wq, Wk, Wv);
    attn_kernel<<<dim3(T_ / 128, H_, B_), 256, SMEM_ATTN>>>();
    proj_kernel<<<dim3((B_ * T_) / 128, E_ / 64), 256, SMEM_PROJ>>>(Wp, bp, out);
}

// round 6
// speedup vs baseline: 2.8460x; 2.8460x over previous
#include <cuda_runtime.h>
#include <cuda_bf16.h>
#include <cstdint>

// Problem constants
constexpr int B_ = 4;
constexpr int T_ = 2048;
constexpr int E_ = 1024;
constexpr int H_ = 16;
constexpr int S_ = 64;

// ---------------------------------------------------------------------------
// Global scratch (bf16 hi/lo split). Static device arrays only.
// ---------------------------------------------------------------------------
__device__ __nv_bfloat16 g_Qh[(size_t)B_ * H_ * T_ * S_];   // (b,h,t,s), pre-scaled
__device__ __nv_bfloat16 g_Ql[(size_t)B_ * H_ * T_ * S_];
__device__ __nv_bfloat16 g_Kh[(size_t)B_ * H_ * T_ * S_];
__device__ __nv_bfloat16 g_Kl[(size_t)B_ * H_ * T_ * S_];
__device__ __nv_bfloat16 g_Vth[(size_t)B_ * H_ * S_ * T_];  // (b,h,s,t) TRANSPOSED
__device__ __nv_bfloat16 g_Vtl[(size_t)B_ * H_ * S_ * T_];
__device__ __nv_bfloat16 g_Ch[(size_t)B_ * T_ * E_];        // context (b,t,e)
__device__ __nv_bfloat16 g_Cl[(size_t)B_ * T_ * E_];
__device__ __nv_bfloat16 g_Wph[(size_t)E_ * E_];
__device__ __nv_bfloat16 g_Wpl[(size_t)E_ * E_];

// ---------------------------------------------------------------------------
// Baseline-PTX helpers (no sm_103a-only instructions!)
// ---------------------------------------------------------------------------
__device__ __forceinline__ uint32_t smem_u32(const void* p) {
    uint32_t a;
    asm("{ .reg .u64 t; cvta.to.shared.u64 t, %1; cvt.u32.u64 %0, t; }"
        : "=r"(a) : "l"(p));
    return a;
}

#define LDS32(r, a) asm volatile("ld.shared.b32 %0, [%1];" : "=r"(r) : "r"(a))

#define CP_ASYNC16(dst, src) \
    asm volatile("cp.async.cg.shared.global [%0], [%1], 16;" :: "r"(dst), "l"(src) : "memory")
#define CP_COMMIT() asm volatile("cp.async.commit_group;" ::: "memory")
#define CP_WAIT1()  asm volatile("cp.async.wait_group 1;" ::: "memory")
#define CP_WAIT0()  asm volatile("cp.async.wait_group 0;" ::: "memory")

// m16n8k16 row.col bf16 -> fp32 accumulate (baseline PTX, runs on HMMA)
__device__ __forceinline__ void mma16816(float d[4], const uint32_t a[4],
                                         uint32_t b0, uint32_t b1) {
    asm volatile(
        "mma.sync.aligned.m16n8k16.row.col.f32.bf16.bf16.f32 "
        "{%0,%1,%2,%3}, {%4,%5,%6,%7}, {%8,%9}, {%0,%1,%2,%3};"
        : "+f"(d[0]), "+f"(d[1]), "+f"(d[2]), "+f"(d[3])
        : "r"(a[0]), "r"(a[1]), "r"(a[2]), "r"(a[3]), "r"(b0), "r"(b1));
}

// hi/lo bf16 split
__device__ __forceinline__ void split2(float v, __nv_bfloat16& h, __nv_bfloat16& l) {
    h = __float2bfloat16(v);
    l = __float2bfloat16(v - __bfloat162float(h));
}
__device__ __forceinline__ uint32_t pack_bf2(__nv_bfloat16 a, __nv_bfloat16 b) {
    __nv_bfloat162 t;
    t.x = a; t.y = b;
    return *reinterpret_cast<uint32_t*>(&t);
}
// split a pair of floats into packed hi-word and lo-word
__device__ __forceinline__ void split_pack(float v0, float v1, uint32_t& hw, uint32_t& lw) {
    __nv_bfloat16 h0, l0, h1, l1;
    split2(v0, h0, l0);
    split2(v1, h1, l1);
    hw = pack_bf2(h0, h1);
    lw = pack_bf2(l0, l1);
}

// ---------------------------------------------------------------------------
// Kernel 1: QKV projection (SIMT) -> bf16 hi/lo in MMA-ready layouts.
// Grid: (T/64, H, 3*B), 256 threads.
// ---------------------------------------------------------------------------
__global__ __launch_bounds__(256) void qkv_kernel(const float* __restrict__ x,
                                                  const float* __restrict__ Wq,
                                                  const float* __restrict__ Wk,
                                                  const float* __restrict__ Wv) {
    extern __shared__ float sm[];
    float(*sW)[65] = (float(*)[65])sm;
    float(*sX)[65] = (float(*)[65])(sm + 64 * 65);

    const int t0 = blockIdx.x * 64;
    const int h = blockIdx.y;
    const int b = blockIdx.z / 3;
    const int which = blockIdx.z % 3;  // 0=Q, 1=K, 2=V
    const int bh = b * H_ + h;
    const int tid = threadIdx.x;

    const float* W = (which == 0) ? Wq : (which == 1) ? Wk : Wv;

    for (int i = tid; i < S_ * S_; i += 256) {
        int r = i >> 6, c = i & 63;
        sW[r][c] = W[i];
    }
    const float* xp = x + ((size_t)b * T_ + t0) * E_ + h * S_;
    for (int i = tid; i < 64 * S_; i += 256) {
        int r = i >> 6, c = i & 63;
        sX[r][c] = xp[(size_t)r * E_ + c];
    }
    __syncthreads();

    const int tx = tid & 15, ty = tid >> 4;
    float acc[4][4] = {};

#pragma unroll 8
    for (int i = 0; i < S_; ++i) {
        float xv[4], wv[4];
#pragma unroll
        for (int ii = 0; ii < 4; ++ii) xv[ii] = sX[ty * 4 + ii][i];
#pragma unroll
        for (int jj = 0; jj < 4; ++jj) wv[jj] = sW[tx * 4 + jj][i];
#pragma unroll
        for (int ii = 0; ii < 4; ++ii)
#pragma unroll
            for (int jj = 0; jj < 4; ++jj) acc[ii][jj] += xv[ii] * wv[jj];
    }

    const float scale = (which < 2) ? 0.17677669529663688f : 1.0f;  // 1/1024^0.25

    if (which < 2) {
        uint32_t* gh = (uint32_t*)(which == 0 ? g_Qh : g_Kh);
        uint32_t* gl = (uint32_t*)(which == 0 ? g_Ql : g_Kl);
#pragma unroll
        for (int ii = 0; ii < 4; ++ii) {
            int t = t0 + ty * 4 + ii;
#pragma unroll
            for (int jj = 0; jj < 4; jj += 2) {
                int o = tx * 4 + jj;
                uint32_t hw, lw;
                split_pack(acc[ii][jj] * scale, acc[ii][jj + 1] * scale, hw, lw);
                size_t w = ((size_t)bh * T_ + t) * 32 + (o >> 1);
                gh[w] = hw;
                gl[w] = lw;
            }
        }
    } else {
        uint32_t* gh = (uint32_t*)g_Vth;
        uint32_t* gl = (uint32_t*)g_Vtl;
#pragma unroll
        for (int jj = 0; jj < 4; ++jj) {
            int s = tx * 4 + jj;
#pragma unroll
            for (int ii = 0; ii < 4; ii += 2) {
                int t = t0 + ty * 4 + ii;
                uint32_t hw, lw;
                split_pack(acc[ii][jj], acc[ii + 1][jj], hw, lw);
                size_t w = ((size_t)bh * 64 + s) * (T_ / 2) + (t >> 1);
                gh[w] = hw;
                gl[w] = lw;
            }
        }
    }
}

// ---------------------------------------------------------------------------
// Kernel 2: Wp -> bf16 hi/lo
// ---------------------------------------------------------------------------
__global__ __launch_bounds__(256) void wp_convert_kernel(const float* __restrict__ Wp) {
    int i = blockIdx.x * 256 + threadIdx.x;
    int stride = gridDim.x * 256;
    for (; i < E_ * E_; i += stride) {
        __nv_bfloat16 h, l;
        split2(Wp[i], h, l);
        g_Wph[i] = h;
        g_Wpl[i] = l;
    }
}

// ---------------------------------------------------------------------------
// Kernel 3: HMMA flash attention. CTA = (b, h, 128 q-rows). 8 warps x 16 rows.
// Q fragments in registers for all 16 KV tiles. K/Vt double-buffered cp.async.
// S C-frags -> exp -> P A-frags IN REGISTERS (no smem P). Max-free softmax.
// Dyn smem: 2 x 71680 = 143360 B.
// ---------------------------------------------------------------------------
constexpr int OFF_KH = 0;          // 128 rows x 144 B  (64 bf16 + 8 pad)
constexpr int OFF_KL = 18432;
constexpr int OFF_VH = 36864;      // 64 rows x 272 B   (128 bf16 + 8 pad)
constexpr int OFF_VL = 54272;
constexpr int BUFSZ  = 71680;
constexpr int ATTN_SMEM = 2 * BUFSZ;   // 143360

__device__ __forceinline__ void attn_load_tile(uint32_t sb, int buf, int bh, int kt,
                                               int tid) {
    uint32_t bb = sb + (buf ? BUFSZ : 0);
    const char* kh = (const char*)g_Kh;
    const char* kl = (const char*)g_Kl;
    const char* vh = (const char*)g_Vth;
    const char* vl = (const char*)g_Vtl;
#pragma unroll
    for (int i = tid; i < 1024; i += 256) {  // K tile: 128 rows x 8 chunks
        int row = i >> 3, c = i & 7;
        long gb = ((long)(bh * T_ + kt + row)) * 128 + c * 16;
        uint32_t so = (uint32_t)(row * 144 + c * 16);
        CP_ASYNC16(bb + OFF_KH + so, kh + gb);
        CP_ASYNC16(bb + OFF_KL + so, kl + gb);
    }
#pragma unroll
    for (int i = tid; i < 1024; i += 256) {  // Vt tile: 64 rows x 16 chunks
        int row = i >> 4, c = i & 15;
        long gb = ((long)(bh * 64 + row)) * (T_ * 2) + (long)kt * 2 + c * 16;
        uint32_t so = (uint32_t)(row * 272 + c * 16);
        CP_ASYNC16(bb + OFF_VH + so, vh + gb);
        CP_ASYNC16(bb + OFF_VL + so, vl + gb);
    }
}

__global__ __launch_bounds__(256, 1) void attn_kernel() {
    extern __shared__ char smc[];
    const uint32_t sb = smem_u32(smc);

    const int tid = threadIdx.x;
    const int w = tid >> 5;
    const int lane = tid & 31;
    const int g = lane >> 2;   // group (row within 8)
    const int tg = lane & 3;   // thread-in-group (col pair)

    const int q0 = blockIdx.x * 128;
    const int bh = blockIdx.z * H_ + blockIdx.y;
    const int r0 = q0 + w * 16 + g;

    // ---- Q fragments from gmem (held for the whole kernel) ----
    uint32_t qh[4][4], ql[4][4];
    {
        const uint32_t* gqh = (const uint32_t*)g_Qh;
        const uint32_t* gql = (const uint32_t*)g_Ql;
        int base0 = (bh * T_ + r0) * 32;
        int base1 = (bh * T_ + r0 + 8) * 32;
#pragma unroll
        for (int kk = 0; kk < 4; ++kk) {
            int wd = kk * 8 + tg;
            qh[kk][0] = gqh[base0 + wd];
            qh[kk][1] = gqh[base1 + wd];
            qh[kk][2] = gqh[base0 + wd + 4];
            qh[kk][3] = gqh[base1 + wd + 4];
            ql[kk][0] = gql[base0 + wd];
            ql[kk][1] = gql[base1 + wd];
            ql[kk][2] = gql[base0 + wd + 4];
            ql[kk][3] = gql[base1 + wd + 4];
        }
    }

    float oacc[8][4] = {};
    float l0 = 0.f, l1 = 0.f;

    attn_load_tile(sb, 0, bh, 0, tid);
    CP_COMMIT();

    for (int it = 0; it < 16; ++it) {
        const int buf = it & 1;
        if (it < 15) {
            attn_load_tile(sb, buf ^ 1, bh, (it + 1) * 128, tid);
            CP_COMMIT();
            CP_WAIT1();
        } else {
            CP_WAIT0();
        }
        __syncthreads();

        const uint32_t kb = sb + (buf ? BUFSZ : 0);

        // ---- S = Q K^T: 16 rows x 128 cols per warp ----
        float sacc[16][4];
#pragma unroll
        for (int nt = 0; nt < 16; ++nt)
#pragma unroll
            for (int j = 0; j < 4; ++j) sacc[nt][j] = 0.f;

#pragma unroll
        for (int kk = 0; kk < 4; ++kk) {
#pragma unroll
            for (int nt = 0; nt < 16; ++nt) {
                uint32_t ah = kb + OFF_KH + (uint32_t)((nt * 8 + g) * 144 + (kk * 8 + tg) * 4);
                uint32_t al = kb + OFF_KL + (uint32_t)((nt * 8 + g) * 144 + (kk * 8 + tg) * 4);
                uint32_t bh0, bh1, bl0, bl1;
                LDS32(bh0, ah);
                LDS32(bh1, ah + 16);
                LDS32(bl0, al);
                LDS32(bl1, al + 16);
                mma16816(sacc[nt], qh[kk], bh0, bh1);
                mma16816(sacc[nt], qh[kk], bl0, bl1);
                mma16816(sacc[nt], ql[kk], bh0, bh1);
            }
        }

        // ---- max-free softmax: P = exp(S); P A-frags built in registers ----
        uint32_t pah[8][4], pal[8][4];
#pragma unroll
        for (int kk = 0; kk < 8; ++kk) {
            float e0 = __expf(sacc[2 * kk][0]);
            float e1 = __expf(sacc[2 * kk][1]);
            float e2 = __expf(sacc[2 * kk][2]);
            float e3 = __expf(sacc[2 * kk][3]);
            float e4 = __expf(sacc[2 * kk + 1][0]);
            float e5 = __expf(sacc[2 * kk + 1][1]);
            float e6 = __expf(sacc[2 * kk + 1][2]);
            float e7 = __expf(sacc[2 * kk + 1][3]);
            l0 += (e0 + e1) + (e4 + e5);
            l1 += (e2 + e3) + (e6 + e7);
            split_pack(e0, e1, pah[kk][0], pal[kk][0]);
            split_pack(e2, e3, pah[kk][1], pal[kk][1]);
            split_pack(e4, e5, pah[kk][2], pal[kk][2]);
            split_pack(e6, e7, pah[kk][3], pal[kk][3]);
        }

        // ---- O += P @ V^T: 16 rows x 64 cols per warp ----
#pragma unroll
        for (int kk = 0; kk < 8; ++kk) {
#pragma unroll
            for (int nt = 0; nt < 8; ++nt) {
                uint32_t ah = kb + OFF_VH + (uint32_t)((nt * 8 + g) * 272 + (kk * 8 + tg) * 4);
                uint32_t al = kb + OFF_VL + (uint32_t)((nt * 8 + g) * 272 + (kk * 8 + tg) * 4);
                uint32_t bh0, bh1, bl0, bl1;
                LDS32(bh0, ah);
                LDS32(bh1, ah + 16);
                LDS32(bl0, al);
                LDS32(bl1, al + 16);
                mma16816(oacc[nt], pah[kk], bh0, bh1);
                mma16816(oacc[nt], pah[kk], bl0, bl1);
                mma16816(oacc[nt], pal[kk], bh0, bh1);
            }
        }
        __syncthreads();
    }

    // ---- epilogue: reduce row sums over quad, normalize, write context ----
    l0 += __shfl_xor_sync(0xffffffffu, l0, 1);
    l0 += __shfl_xor_sync(0xffffffffu, l0, 2);
    l1 += __shfl_xor_sync(0xffffffffu, l1, 1);
    l1 += __shfl_xor_sync(0xffffffffu, l1, 2);
    const float inv0 = 1.0f / l0;
    const float inv1 = 1.0f / l1;

    uint32_t* ch = (uint32_t*)g_Ch;
    uint32_t* cl = (uint32_t*)g_Cl;
    const long wb0 = (long)(blockIdx.z * T_ + r0) * 512 + blockIdx.y * 32;
    const long wb1 = (long)(blockIdx.z * T_ + r0 + 8) * 512 + blockIdx.y * 32;
#pragma unroll
    for (int nt = 0; nt < 8; ++nt) {
        uint32_t hw, lw;
        split_pack(oacc[nt][0] * inv0, oacc[nt][1] * inv0, hw, lw);
        ch[wb0 + nt * 4 + tg] = hw;
        cl[wb0 + nt * 4 + tg] = lw;
        split_pack(oacc[nt][2] * inv1, oacc[nt][3] * inv1, hw, lw);
        ch[wb1 + nt * 4 + tg] = hw;
        cl[wb1 + nt * 4 + tg] = lw;
    }
}

// ---------------------------------------------------------------------------
// Kernel 4: HMMA output projection. Y = C @ Wp^T + bp.
// M=8192, N=K=1024. CTA tile 128x128, K-chunks of 64, double-buffered cp.async.
// Grid (64, 8), 256 threads. Dyn smem: 2 x 73728 = 147456 B.
// ---------------------------------------------------------------------------
constexpr int PJ_AH = 0;           // 128 x 144 B
constexpr int PJ_AL = 18432;
constexpr int PJ_BH = 36864;
constexpr int PJ_BL = 55296;
constexpr int PJ_BUF = 73728;
constexpr int PROJ_SMEM = 2 * PJ_BUF;  // 147456

__device__ __forceinline__ void proj_load_tile(uint32_t sb, int buf, int m0, int n0,
                                               int kc, int tid) {
    uint32_t bb = sb + (buf ? PJ_BUF : 0);
    const char* ah = (const char*)g_Ch;
    const char* al = (const char*)g_Cl;
    const char* bh = (const char*)g_Wph;
    const char* bl = (const char*)g_Wpl;
#pragma unroll
    for (int i = tid; i < 1024; i += 256) {  // 128 rows x 8 chunks of 16B
        int row = i >> 3, c = i & 7;
        uint32_t so = (uint32_t)(row * 144 + c * 16);
        long ga = ((long)(m0 + row) * E_ + kc * 64) * 2 + c * 16;
        long gb = ((long)(n0 + row) * E_ + kc * 64) * 2 + c * 16;
        CP_ASYNC16(bb + PJ_AH + so, ah + ga);
        CP_ASYNC16(bb + PJ_AL + so, al + ga);
        CP_ASYNC16(bb + PJ_BH + so, bh + gb);
        CP_ASYNC16(bb + PJ_BL + so, bl + gb);
    }
}

__global__ __launch_bounds__(256, 1) void proj_kernel(const float* __restrict__ bp,
                                                      float* __restrict__ out) {
    extern __shared__ char smc[];
    const uint32_t sb = smem_u32(smc);

    const int tid = threadIdx.x;
    const int w = tid >> 5;
    const int lane = tid & 31;
    const int g = lane >> 2;
    const int tg = lane & 3;

    const int m0 = blockIdx.x * 128;
    const int n0 = blockIdx.y * 128;

    float acc[16][4] = {};

    proj_load_tile(sb, 0, m0, n0, 0, tid);
    CP_COMMIT();

    for (int kc = 0; kc < 16; ++kc) {
        const int buf = kc & 1;
        if (kc < 15) {
            proj_load_tile(sb, buf ^ 1, m0, n0, kc + 1, tid);
            CP_COMMIT();
            CP_WAIT1();
        } else {
            CP_WAIT0();
        }
        __syncthreads();

        const uint32_t bb = sb + (buf ? PJ_BUF : 0);
        const uint32_t arow0 = (uint32_t)((w * 16 + g) * 144);
        const uint32_t arow1 = arow0 + 8 * 144;

#pragma unroll
        for (int kk = 0; kk < 4; ++kk) {
            uint32_t fah[4], fal[4];
            uint32_t wo = (uint32_t)((kk * 8 + tg) * 4);
            LDS32(fah[0], bb + PJ_AH + arow0 + wo);
            LDS32(fah[1], bb + PJ_AH + arow1 + wo);
            LDS32(fah[2], bb + PJ_AH + arow0 + wo + 16);
            LDS32(fah[3], bb + PJ_AH + arow1 + wo + 16);
            LDS32(fal[0], bb + PJ_AL + arow0 + wo);
            LDS32(fal[1], bb + PJ_AL + arow1 + wo);
            LDS32(fal[2], bb + PJ_AL + arow0 + wo + 16);
            LDS32(fal[3], bb + PJ_AL + arow1 + wo + 16);
#pragma unroll
            for (int nt = 0; nt < 16; ++nt) {
                uint32_t boff = (uint32_t)((nt * 8 + g) * 144) + wo;
                uint32_t bh0, bh1, bl0, bl1;
                LDS32(bh0, bb + PJ_BH + boff);
                LDS32(bh1, bb + PJ_BH + boff + 16);
                LDS32(bl0, bb + PJ_BL + boff);
                LDS32(bl1, bb + PJ_BL + boff + 16);
                mma16816(acc[nt], fah, bh0, bh1);
                mma16816(acc[nt], fah, bl0, bl1);
                mma16816(acc[nt], fal, bh0, bh1);
            }
        }
        __syncthreads();
    }

    // epilogue: add bias, write fp32
    const int mr0 = m0 + w * 16 + g;
    const int mr1 = mr0 + 8;
#pragma unroll
    for (int nt = 0; nt < 8 + 8; ++nt) {
        int col = n0 + nt * 8 + tg * 2;
        float b0 = __ldg(bp + col);
        float b1 = __ldg(bp + col + 1);
        float2 v0 = make_float2(acc[nt][0] + b0, acc[nt][1] + b1);
        float2 v1 = make_float2(acc[nt][2] + b0, acc[nt][3] + b1);
        *(float2*)(out + (long)mr0 * E_ + col) = v0;
        *(float2*)(out + (long)mr1 * E_ + col) = v1;
    }
}

// ---------------------------------------------------------------------------
// kernel_launch: inputs x, Wk, Wq, Wv, Wp, bp
// ---------------------------------------------------------------------------
extern "C" void kernel_launch(void* const* d_in, const int* in_sizes, int n_in,
                              void* d_out, int out_size) {
    (void)in_sizes; (void)n_in; (void)out_size;
    const float* x = (const float*)d_in[0];
    const float* Wk = (const float*)d_in[1];
    const float* Wq = (const float*)d_in[2];
    const float* Wv = (const float*)d_in[3];
    const float* Wp = (const float*)d_in[4];
    const float* bp = (const float*)d_in[5];
    float* out = (float*)d_out;

    constexpr int SMEM_QKV = 128 * 65 * 4;  // 33280

    cudaFuncSetAttribute(qkv_kernel, cudaFuncAttributeMaxDynamicSharedMemorySize, SMEM_QKV);
    cudaFuncSetAttribute(attn_kernel, cudaFuncAttributeMaxDynamicSharedMemorySize, ATTN_SMEM);
    cudaFuncSetAttribute(proj_kernel, cudaFuncAttributeMaxDynamicSharedMemorySize, PROJ_SMEM);

    qkv_kernel<<<dim3(T_ / 64, H_, 3 * B_), 256, SMEM_QKV>>>(x, Wq, Wk, Wv);
    wp_convert_kernel<<<256, 256>>>(Wp);
    attn_kernel<<<dim3(T_ / 128, H_, B_), 256, ATTN_SMEM>>>();
    proj_kernel<<<dim3((B_ * T_) / 128, E_ / 128), 256, PROJ_SMEM>>>(bp, out);
}